// round 1
// baseline (speedup 1.0000x reference)
#include <cuda_runtime.h>

typedef unsigned long long ULL;

// ---------- packed f32x2 helpers (FFMA2 only reachable via PTX) ----------
__device__ __forceinline__ ULL pack2(float a, float b) {
    ULL r; asm("mov.b64 %0, {%1, %2};" : "=l"(r) : "f"(a), "f"(b)); return r;
}
__device__ __forceinline__ float2 unpack2(ULL v) {
    float lo, hi; asm("mov.b64 {%0, %1}, %2;" : "=f"(lo), "=f"(hi) : "l"(v));
    return make_float2(lo, hi);
}
__device__ __forceinline__ void ffma2(ULL& d, ULL a, ULL b) {
    asm("fma.rn.f32x2 %0, %1, %2, %0;" : "+l"(d) : "l"(a), "l"(b));
}

// ---------- scratch: planes transposed to (plane, H, W, C) ----------
__device__ float g_planes[3 * 256 * 256 * 32];

__global__ void transpose_kernel(const float* __restrict__ pxy,
                                 const float* __restrict__ pxz,
                                 const float* __restrict__ pyz) {
    __shared__ float tile[32][33];
    const float* src = blockIdx.z == 0 ? pxy : (blockIdx.z == 1 ? pxz : pyz);
    const int x0 = blockIdx.x * 32;
    const int y  = blockIdx.y;
    // load: rows = channel, cols = x (coalesced along x)
    tile[threadIdx.y][threadIdx.x] = src[threadIdx.y * 65536 + y * 256 + x0 + threadIdx.x];
    __syncthreads();
    // store: consecutive channels contiguous (coalesced along c)
    g_planes[((blockIdx.z * 256 + y) * 256 + (x0 + threadIdx.y)) * 32 + threadIdx.x] =
        tile[threadIdx.x][threadIdx.y];
}

// ---------- gather one plane's 32 features and accumulate into layer-1 ----------
__device__ __forceinline__ void accum_plane(ULL* __restrict__ acc,
                                            const float* __restrict__ Wrow,   // 32 rows x 64 (shared)
                                            const float* __restrict__ pb,     // plane base (H,W,C)
                                            int u0, int u1, int v0, int v1,
                                            float fu, float fv) {
    const float* r00 = pb + (v0 * 256 + u0) * 32;
    const float* r01 = pb + (v0 * 256 + u1) * 32;
    const float* r10 = pb + (v1 * 256 + u0) * 32;
    const float* r11 = pb + (v1 * 256 + u1) * 32;
    const float w00 = (1.f - fu) * (1.f - fv);
    const float w01 = fu * (1.f - fv);
    const float w10 = (1.f - fu) * fv;
    const float w11 = fu * fv;
#pragma unroll 2
    for (int cb = 0; cb < 32; cb += 4) {
        float4 a = *(const float4*)(r00 + cb);
        float4 b = *(const float4*)(r01 + cb);
        float4 c = *(const float4*)(r10 + cb);
        float4 d = *(const float4*)(r11 + cb);
        float f[4];
        f[0] = a.x * w00 + b.x * w01 + c.x * w10 + d.x * w11;
        f[1] = a.y * w00 + b.y * w01 + c.y * w10 + d.y * w11;
        f[2] = a.z * w00 + b.z * w01 + c.z * w10 + d.z * w11;
        f[3] = a.w * w00 + b.w * w01 + c.w * w10 + d.w * w11;
#pragma unroll
        for (int q = 0; q < 4; q++) {
            ULL fp = pack2(f[q], f[q]);
            const ulonglong2* wr = (const ulonglong2*)(Wrow + (cb + q) * 64);
#pragma unroll
            for (int j = 0; j < 16; j++) {
                ulonglong2 wv = wr[j];
                ffma2(acc[2 * j],     wv.x, fp);
                ffma2(acc[2 * j + 1], wv.y, fp);
            }
        }
    }
}

// ---------- packed dense layer: 2*NINP scalar inputs -> 2*NOUTP outputs ----------
template <int NINP, int NOUTP>
__device__ __forceinline__ void dense_packed(ULL* __restrict__ out,
                                             const ULL* __restrict__ in,
                                             const float* __restrict__ W) {
#pragma unroll
    for (int j = 0; j < NOUTP; j++) out[j] = 0ULL;
#pragma unroll
    for (int jp = 0; jp < NINP; jp++) {
        float2 v = unpack2(in[jp]);
        ULL f0 = pack2(v.x, v.x);
        ULL f1 = pack2(v.y, v.y);
        const ulonglong2* wr0 = (const ulonglong2*)(W + (2 * jp)     * (2 * NOUTP));
        const ulonglong2* wr1 = (const ulonglong2*)(W + (2 * jp + 1) * (2 * NOUTP));
#pragma unroll
        for (int j = 0; j < NOUTP / 2; j++) {
            ulonglong2 w0 = wr0[j];
            ffma2(out[2 * j],     w0.x, f0);
            ffma2(out[2 * j + 1], w0.y, f0);
        }
#pragma unroll
        for (int j = 0; j < NOUTP / 2; j++) {
            ulonglong2 w1 = wr1[j];
            ffma2(out[2 * j],     w1.x, f1);
            ffma2(out[2 * j + 1], w1.y, f1);
        }
    }
}

static constexpr int NPTS = 1048576;

__global__ __launch_bounds__(128)
void nerf_kernel(const float* __restrict__ xin,
                 const float* __restrict__ center,
                 const float* __restrict__ scale,
                 const float* __restrict__ w1,   // (96,64)
                 const float* __restrict__ w2,   // (64,16)
                 const float* __restrict__ w3,   // (15,64)
                 const float* __restrict__ w4,   // (64,64)
                 const float* __restrict__ w5,   // (64,3)
                 float* __restrict__ out) {
    __shared__ __align__(16) float sW1[96 * 64];
    __shared__ __align__(16) float sW2[64 * 16];
    __shared__ __align__(16) float sW3[15 * 64];
    __shared__ __align__(16) float sW4[64 * 64];

    const int tid = threadIdx.x;
    for (int i = tid; i < 96 * 64; i += 128) sW1[i] = w1[i];
    for (int i = tid; i < 64 * 16; i += 128) sW2[i] = w2[i];
    for (int i = tid; i < 15 * 64; i += 128) sW3[i] = w3[i];
    for (int i = tid; i < 64 * 64; i += 128) sW4[i] = w4[i];
    __syncthreads();

    const int pid = blockIdx.x * 128 + tid;
    const float px = xin[3 * pid + 0];
    const float py = xin[3 * pid + 1];
    const float pz = xin[3 * pid + 2];

    // normalize per axis: xn = clip((x-c)/s + 0.5, 0, 1); grid coord = xn * 255
    float vx = fminf(fmaxf((px - center[0]) / scale[0] + 0.5f, 0.f), 1.f) * 255.f;
    float vy = fminf(fmaxf((py - center[1]) / scale[1] + 0.5f, 0.f), 1.f) * 255.f;
    float vz = fminf(fmaxf((pz - center[2]) / scale[2] + 0.5f, 0.f), 1.f) * 255.f;

    float flx = floorf(vx), fly = floorf(vy), flz = floorf(vz);
    float fx = vx - flx, fy = vy - fly, fz = vz - flz;
    int x0i = (int)flx; int x1i = min(x0i + 1, 255);
    int y0i = (int)fly; int y1i = min(y0i + 1, 255);
    int z0i = (int)flz; int z1i = min(z0i + 1, 255);

    // ---- layer 1: feat(96) @ W1(96,64), feat streamed from plane gathers ----
    ULL acc[32];
#pragma unroll
    for (int j = 0; j < 32; j++) acc[j] = 0ULL;

    // feat_xy: gu=x, gv=y ; feat_xz: gu=x, gv=z ; feat_yz: gu=y, gv=z
    accum_plane(acc, sW1,            g_planes,                 x0i, x1i, y0i, y1i, fx, fy);
    accum_plane(acc, sW1 + 32 * 64,  g_planes + 65536 * 32,     x0i, x1i, z0i, z1i, fx, fz);
    accum_plane(acc, sW1 + 64 * 64,  g_planes + 2 * 65536 * 32, y0i, y1i, z0i, z1i, fy, fz);

    // relu
#pragma unroll
    for (int j = 0; j < 32; j++) {
        float2 v = unpack2(acc[j]);
        acc[j] = pack2(fmaxf(v.x, 0.f), fmaxf(v.y, 0.f));
    }

    // ---- layer 2: h(64) @ W2(64,16) ----
    ULL b16[8];
    dense_packed<32, 8>(b16, acc, sW2);
    float o[16];
#pragma unroll
    for (int j = 0; j < 8; j++) {
        float2 v = unpack2(b16[j]);
        o[2 * j] = v.x; o[2 * j + 1] = v.y;
    }
    const float sigma = o[0];

    // ---- layer 3: o[1..15] @ W3(15,64), relu -> reuse acc ----
#pragma unroll
    for (int j = 0; j < 32; j++) acc[j] = 0ULL;
#pragma unroll
    for (int k = 0; k < 15; k++) {
        ULL fp = pack2(o[k + 1], o[k + 1]);
        const ulonglong2* wr = (const ulonglong2*)(sW3 + k * 64);
#pragma unroll
        for (int j = 0; j < 16; j++) {
            ulonglong2 wv = wr[j];
            ffma2(acc[2 * j],     wv.x, fp);
            ffma2(acc[2 * j + 1], wv.y, fp);
        }
    }
#pragma unroll
    for (int j = 0; j < 32; j++) {
        float2 v = unpack2(acc[j]);
        acc[j] = pack2(fmaxf(v.x, 0.f), fmaxf(v.y, 0.f));
    }

    // ---- layer 4: c1(64) @ W4(64,64), relu ----
    ULL c2[32];
    dense_packed<32, 32>(c2, acc, sW4);
#pragma unroll
    for (int j = 0; j < 32; j++) {
        float2 v = unpack2(c2[j]);
        c2[j] = pack2(fmaxf(v.x, 0.f), fmaxf(v.y, 0.f));
    }

    // ---- layer 5: c2(64) @ W5(64,3), sigmoid ----
    float cr = 0.f, cg = 0.f, cb = 0.f;
#pragma unroll
    for (int j = 0; j < 32; j++) {
        float2 v = unpack2(c2[j]);
        cr += v.x * w5[6 * j + 0] + v.y * w5[6 * j + 3];
        cg += v.x * w5[6 * j + 1] + v.y * w5[6 * j + 4];
        cb += v.x * w5[6 * j + 2] + v.y * w5[6 * j + 5];
    }
    cr = 1.f / (1.f + __expf(-cr));
    cg = 1.f / (1.f + __expf(-cg));
    cb = 1.f / (1.f + __expf(-cb));

    // output: color (N,3) then sigma (N)
    out[3 * pid + 0] = cr;
    out[3 * pid + 1] = cg;
    out[3 * pid + 2] = cb;
    out[3 * NPTS + pid] = sigma;
}

extern "C" void kernel_launch(void* const* d_in, const int* in_sizes, int n_in,
                              void* d_out, int out_size) {
    const float* x      = (const float*)d_in[0];
    // d_in[1] = view directions d: unused by the reference network
    const float* pxy    = (const float*)d_in[2];
    const float* pxz    = (const float*)d_in[3];
    const float* pyz    = (const float*)d_in[4];
    const float* center = (const float*)d_in[5];
    const float* scale  = (const float*)d_in[6];
    const float* w1     = (const float*)d_in[7];
    const float* w2     = (const float*)d_in[8];
    const float* w3     = (const float*)d_in[9];
    const float* w4     = (const float*)d_in[10];
    const float* w5     = (const float*)d_in[11];

    dim3 tb(32, 32), tg(8, 256, 3);
    transpose_kernel<<<tg, tb>>>(pxy, pxz, pyz);
    nerf_kernel<<<NPTS / 128, 128>>>(x, center, scale, w1, w2, w3, w4, w5, (float*)d_out);
}

// round 3
// speedup vs baseline: 2.1351x; 2.1351x over previous
#include <cuda_runtime.h>
#include <cuda_fp16.h>

typedef unsigned int u32;

static constexpr int NPTS  = 1048576;
static constexpr int TILES = NPTS / 128;   // 8192
static constexpr int NBLK  = 296;          // 2 CTAs/SM * 148 SMs
static constexpr int SFSTR = 100;          // staged row stride (floats), 100%32==4 -> conflict-free phases
static constexpr int SF_BYTES = 128 * SFSTR * 4;          // 51200
static constexpr int NFRAG = 100;                         // weight fragments
static constexpr int SMEM_TOTAL = SF_BYTES + NFRAG * 512; // 102400

// ---------------- planes transposed to (plane, H, W, C) ----------------
__device__ float g_planes[3 * 256 * 256 * 32];

__global__ void transpose_kernel(const float* __restrict__ pxy,
                                 const float* __restrict__ pxz,
                                 const float* __restrict__ pyz) {
    __shared__ float tile[32][33];
    const float* src = blockIdx.z == 0 ? pxy : (blockIdx.z == 1 ? pxz : pyz);
    const int x0 = blockIdx.x * 32;
    const int y  = blockIdx.y;
    tile[threadIdx.y][threadIdx.x] = src[threadIdx.y * 65536 + y * 256 + x0 + threadIdx.x];
    __syncthreads();
    g_planes[((blockIdx.z * 256 + y) * 256 + (x0 + threadIdx.y)) * 32 + threadIdx.x] =
        tile[threadIdx.x][threadIdx.y];
}

// ---------------- helpers ----------------
__device__ __forceinline__ void split2(float a, float b, u32& hi, u32& lo) {
    half2 h = __floats2half2_rn(a, b);
    float2 hf = __half22float2(h);
    half2 l = __floats2half2_rn(a - hf.x, b - hf.y);
    hi = *reinterpret_cast<u32*>(&h);
    lo = *reinterpret_cast<u32*>(&l);
}

__device__ __forceinline__ void mma16(float* d, const u32* a, u32 b0, u32 b1) {
    asm volatile("mma.sync.aligned.m16n8k16.row.col.f32.f16.f16.f32 "
                 "{%0,%1,%2,%3}, {%4,%5,%6,%7}, {%8,%9}, {%0,%1,%2,%3};"
                 : "+f"(d[0]), "+f"(d[1]), "+f"(d[2]), "+f"(d[3])
                 : "r"(a[0]), "r"(a[1]), "r"(a[2]), "r"(a[3]), "r"(b0), "r"(b1));
}

// one mma-triple: D += (Ahi+Alo)(Bhi+Blo) - Alo*Blo (negligible)
__device__ __forceinline__ void mma3(float* d, const u32* ah, const u32* al, uint4 B) {
    mma16(d, ah, B.x, B.y);
    mma16(d, al, B.x, B.y);
    mma16(d, ah, B.z, B.w);
}

// build next-layer A fragment from two D n-tiles (register-local repack)
__device__ __forceinline__ void build_a_relu(const float* s0, const float* s1,
                                             u32* ah, u32* al) {
    split2(fmaxf(s0[0], 0.f), fmaxf(s0[1], 0.f), ah[0], al[0]);
    split2(fmaxf(s0[2], 0.f), fmaxf(s0[3], 0.f), ah[1], al[1]);
    split2(fmaxf(s1[0], 0.f), fmaxf(s1[1], 0.f), ah[2], al[2]);
    split2(fmaxf(s1[2], 0.f), fmaxf(s1[3], 0.f), ah[3], al[3]);
}
__device__ __forceinline__ void build_a(const float* s0, const float* s1,
                                        u32* ah, u32* al) {
    split2(s0[0], s0[1], ah[0], al[0]);
    split2(s0[2], s0[3], ah[1], al[1]);
    split2(s1[0], s1[1], ah[2], al[2]);
    split2(s1[2], s1[3], ah[3], al[3]);
}

// gather one plane's 32 bilinear features
__device__ __forceinline__ void gather32f(float* fr, const float* __restrict__ pb,
                                          int u0, int u1, int v0, int v1,
                                          float fu, float fv) {
    const float* r00 = pb + (v0 * 256 + u0) * 32;
    const float* r01 = pb + (v0 * 256 + u1) * 32;
    const float* r10 = pb + (v1 * 256 + u0) * 32;
    const float* r11 = pb + (v1 * 256 + u1) * 32;
    const float w00 = (1.f - fu) * (1.f - fv);
    const float w01 = fu * (1.f - fv);
    const float w10 = (1.f - fu) * fv;
    const float w11 = fu * fv;
#pragma unroll
    for (int cb = 0; cb < 32; cb += 4) {
        float4 a = *(const float4*)(r00 + cb);
        float4 b = *(const float4*)(r01 + cb);
        float4 c = *(const float4*)(r10 + cb);
        float4 d = *(const float4*)(r11 + cb);
        fr[cb + 0] = a.x * w00 + b.x * w01 + c.x * w10 + d.x * w11;
        fr[cb + 1] = a.y * w00 + b.y * w01 + c.y * w10 + d.y * w11;
        fr[cb + 2] = a.z * w00 + b.z * w01 + c.z * w10 + d.z * w11;
        fr[cb + 3] = a.w * w00 + b.w * w01 + c.w * w10 + d.w * w11;
    }
}

__device__ __forceinline__ float sigm(float x) { return 1.f / (1.f + __expf(-x)); }

// weight fragment table layout (frag index -> layer tile):
//  [0,48):  W1 (96,64)   kt=f/8, nt=f%8
//  [48,56): W2 (64,16)   kt=(f-48)/2, nt=(f-48)%2
//  [56,64): W3'(16,64)   kt=0, nt=f-56   (row0 = 0: sigma column masked)
//  [64,96): W4 (64,64)   kt=(f-64)/8, nt=(f-64)%8
//  [96,100):W5'(64,8)    kt=f-96, nt=0   (cols>=3 = 0)

__global__ __launch_bounds__(128)
void nerf_mma(const float* __restrict__ xin,
              const float* __restrict__ center,
              const float* __restrict__ scale,
              const float* __restrict__ w1,
              const float* __restrict__ w2,
              const float* __restrict__ w3,
              const float* __restrict__ w4,
              const float* __restrict__ w5,
              float* __restrict__ out) {
    extern __shared__ __align__(16) char smem[];
    float* sf = (float*)smem;
    uint4* swf = (uint4*)(smem + SF_BYTES);

    const int tid  = threadIdx.x;
    const int wid  = tid >> 5;
    const int lane = tid & 31;
    const int g  = lane >> 2;        // fragment row group
    const int t2 = (lane & 3) * 2;   // fragment col pair

    // ---- build weight fragments (hi/lo fp16, fragment order) ----
    for (int f = wid; f < NFRAG; f += 4) {
        float v0, v1, v2, v3;
        if (f < 48) {
            int kt = f >> 3, nt = f & 7;
            int ka = kt * 16 + t2, n = nt * 8 + g;
            v0 = w1[ka * 64 + n];       v1 = w1[(ka + 1) * 64 + n];
            v2 = w1[(ka + 8) * 64 + n]; v3 = w1[(ka + 9) * 64 + n];
        } else if (f < 56) {
            int q = f - 48, kt = q >> 1, nt = q & 1;
            int ka = kt * 16 + t2, n = nt * 8 + g;
            v0 = w2[ka * 16 + n];       v1 = w2[(ka + 1) * 16 + n];
            v2 = w2[(ka + 8) * 16 + n]; v3 = w2[(ka + 9) * 16 + n];
        } else if (f < 64) {
            int nt = f - 56;
            int ka = t2, n = nt * 8 + g;          // k in [0,16): elem = k==0 ? 0 : w3[k-1][n]
            v0 = (ka == 0) ? 0.f : w3[(ka - 1) * 64 + n];
            v1 = w3[ka * 64 + n];
            v2 = w3[(ka + 7) * 64 + n];
            v3 = w3[(ka + 8) * 64 + n];
        } else if (f < 96) {
            int q = f - 64, kt = q >> 3, nt = q & 7;
            int ka = kt * 16 + t2, n = nt * 8 + g;
            v0 = w4[ka * 64 + n];       v1 = w4[(ka + 1) * 64 + n];
            v2 = w4[(ka + 8) * 64 + n]; v3 = w4[(ka + 9) * 64 + n];
        } else {
            int kt = f - 96;
            int ka = kt * 16 + t2, n = g;          // cols >= 3 are zero
            v0 = (n < 3) ? w5[ka * 3 + n] : 0.f;
            v1 = (n < 3) ? w5[(ka + 1) * 3 + n] : 0.f;
            v2 = (n < 3) ? w5[(ka + 8) * 3 + n] : 0.f;
            v3 = (n < 3) ? w5[(ka + 9) * 3 + n] : 0.f;
        }
        uint4 q;
        split2(v0, v1, q.x, q.z);
        split2(v2, v3, q.y, q.w);
        swf[f * 32 + lane] = q;
    }
    __syncthreads();

    const float c0 = center[0], c1 = center[1], c2 = center[2];
    const float s0 = scale[0],  s1 = scale[1],  s2 = scale[2];
    const int rw = wid * 32;

    for (int tile = blockIdx.x; tile < TILES; tile += gridDim.x) {
        const int pid = tile * 128 + tid;
        const float px = xin[3 * pid + 0];
        const float py = xin[3 * pid + 1];
        const float pz = xin[3 * pid + 2];

        float vx = fminf(fmaxf((px - c0) / s0 + 0.5f, 0.f), 1.f) * 255.f;
        float vy = fminf(fmaxf((py - c1) / s1 + 0.5f, 0.f), 1.f) * 255.f;
        float vz = fminf(fmaxf((pz - c2) / s2 + 0.5f, 0.f), 1.f) * 255.f;
        float flx = floorf(vx), fly = floorf(vy), flz = floorf(vz);
        float fx = vx - flx, fy = vy - fly, fz = vz - flz;
        int x0i = (int)flx, x1i = min(x0i + 1, 255);
        int y0i = (int)fly, y1i = min(y0i + 1, 255);
        int z0i = (int)flz, z1i = min(z0i + 1, 255);

        // ---- stage features into smem (warp-private rows) ----
        __syncwarp();
        {
            float fr[32];
            gather32f(fr, g_planes, x0i, x1i, y0i, y1i, fx, fy);
#pragma unroll
            for (int i = 0; i < 8; i++)
                *(float4*)&sf[tid * SFSTR + i * 4] = *(float4*)&fr[i * 4];
            gather32f(fr, g_planes + 65536 * 32, x0i, x1i, z0i, z1i, fx, fz);
#pragma unroll
            for (int i = 0; i < 8; i++)
                *(float4*)&sf[tid * SFSTR + 32 + i * 4] = *(float4*)&fr[i * 4];
            gather32f(fr, g_planes + 2 * 65536 * 32, y0i, y1i, z0i, z1i, fy, fz);
#pragma unroll
            for (int i = 0; i < 8; i++)
                *(float4*)&sf[tid * SFSTR + 64 + i * 4] = *(float4*)&fr[i * 4];
        }
        __syncwarp();

        // ---- per m16-tile MLP (mt outer keeps registers low) ----
#pragma unroll
        for (int mt = 0; mt < 2; mt++) {
            // L1: [16x96] @ W1 -> D1[8 ntiles]
            float D1[8][4];
#pragma unroll
            for (int n = 0; n < 8; n++)
#pragma unroll
                for (int q = 0; q < 4; q++) D1[n][q] = 0.f;
#pragma unroll
            for (int kt = 0; kt < 6; kt++) {
                u32 ah[4], al[4];
                const float* rp = &sf[(rw + mt * 16 + g) * SFSTR + kt * 16 + t2];
                float2 p0 = *(const float2*)rp;
                float2 p1 = *(const float2*)(rp + 8 * SFSTR);
                float2 p2 = *(const float2*)(rp + 8);
                float2 p3 = *(const float2*)(rp + 8 * SFSTR + 8);
                split2(p0.x, p0.y, ah[0], al[0]);
                split2(p1.x, p1.y, ah[1], al[1]);
                split2(p2.x, p2.y, ah[2], al[2]);
                split2(p3.x, p3.y, ah[3], al[3]);
#pragma unroll
                for (int nt = 0; nt < 8; nt++)
                    mma3(D1[nt], ah, al, swf[(kt * 8 + nt) * 32 + lane]);
            }

            // L2: relu(D1)[16x64] @ W2 -> D2[2 ntiles]
            float D2[2][4];
#pragma unroll
            for (int n = 0; n < 2; n++)
#pragma unroll
                for (int q = 0; q < 4; q++) D2[n][q] = 0.f;
#pragma unroll
            for (int kt = 0; kt < 4; kt++) {
                u32 ah[4], al[4];
                build_a_relu(D1[2 * kt], D1[2 * kt + 1], ah, al);
#pragma unroll
                for (int nt = 0; nt < 2; nt++)
                    mma3(D2[nt], ah, al, swf[(48 + kt * 2 + nt) * 32 + lane]);
            }

            // L3: out16[16x16] @ W3' -> D3[8] (no relu on out16; W3' row0=0)
            float D3[8][4];
#pragma unroll
            for (int n = 0; n < 8; n++)
#pragma unroll
                for (int q = 0; q < 4; q++) D3[n][q] = 0.f;
            {
                u32 ah[4], al[4];
                build_a(D2[0], D2[1], ah, al);
#pragma unroll
                for (int nt = 0; nt < 8; nt++)
                    mma3(D3[nt], ah, al, swf[(56 + nt) * 32 + lane]);
            }

            // L4: relu(D3)[16x64] @ W4 -> D4[8]
            float D4[8][4];
#pragma unroll
            for (int n = 0; n < 8; n++)
#pragma unroll
                for (int q = 0; q < 4; q++) D4[n][q] = 0.f;
#pragma unroll
            for (int kt = 0; kt < 4; kt++) {
                u32 ah[4], al[4];
                build_a_relu(D3[2 * kt], D3[2 * kt + 1], ah, al);
#pragma unroll
                for (int nt = 0; nt < 8; nt++)
                    mma3(D4[nt], ah, al, swf[(64 + kt * 8 + nt) * 32 + lane]);
            }

            // L5: relu(D4)[16x64] @ W5' -> D5 (cols 0..2 = color)
            float D5[4] = {0.f, 0.f, 0.f, 0.f};
#pragma unroll
            for (int kt = 0; kt < 4; kt++) {
                u32 ah[4], al[4];
                build_a_relu(D4[2 * kt], D4[2 * kt + 1], ah, al);
                mma3(D5, ah, al, swf[(96 + kt) * 32 + lane]);
            }

            // ---- epilogue ----
            const int r0 = tile * 128 + rw + mt * 16 + g;
            const int r1 = r0 + 8;
            const int lm = lane & 3;
            if (lm == 0) {
                out[3 * r0 + 0] = sigm(D5[0]);
                out[3 * r0 + 1] = sigm(D5[1]);
                out[3 * r1 + 0] = sigm(D5[2]);
                out[3 * r1 + 1] = sigm(D5[3]);
                out[3 * NPTS + r0] = D2[0][0];   // sigma = out16 col0
                out[3 * NPTS + r1] = D2[0][2];
            } else if (lm == 1) {
                out[3 * r0 + 2] = sigm(D5[0]);
                out[3 * r1 + 2] = sigm(D5[2]);
            }
        }
    }
}

extern "C" void kernel_launch(void* const* d_in, const int* in_sizes, int n_in,
                              void* d_out, int out_size) {
    const float* x      = (const float*)d_in[0];
    const float* pxy    = (const float*)d_in[2];
    const float* pxz    = (const float*)d_in[3];
    const float* pyz    = (const float*)d_in[4];
    const float* center = (const float*)d_in[5];
    const float* scale  = (const float*)d_in[6];
    const float* w1     = (const float*)d_in[7];
    const float* w2     = (const float*)d_in[8];
    const float* w3     = (const float*)d_in[9];
    const float* w4     = (const float*)d_in[10];
    const float* w5     = (const float*)d_in[11];

    cudaFuncSetAttribute(nerf_mma, cudaFuncAttributeMaxDynamicSharedMemorySize, SMEM_TOTAL);

    dim3 tb(32, 32), tg(8, 256, 3);
    transpose_kernel<<<tg, tb>>>(pxy, pxz, pyz);
    nerf_mma<<<NBLK, 128, SMEM_TOTAL>>>(x, center, scale, w1, w2, w3, w4, w5, (float*)d_out);
}